// round 13
// baseline (speedup 1.0000x reference)
#include <cuda_runtime.h>
#include <cuda_bf16.h>
#include <math.h>

#define BB 32
#define TT 256
#define AA 22
#define FIN 16
#define CC 128
#define HC 512
#define HID 256
#define G4 1024
#define NF (BB*TT)        // 8192 frames

// ---------------- device scratch (static allocations only) ----------------
__device__ float g_pooled[NF*CC];          // 4 MB
__device__ float g_xg[NF*G4];              // 32 MB (layer-0 input transform)
__device__ float g_hlast[BB*HID];

// dtype-robust seq_length read (JAX x64-off => int32 even though ref says int64)
__device__ __forceinline__ int read_len(const int* p, int b)
{
    bool is64 = (p[1] == 0) && (p[3] == 0);
    return is64 ? p[2*b] : p[b];
}

// fast, accurate-enough nonlinearities (errors ~1e-7, budget is 1e-3)
__device__ __forceinline__ float sig_fast(float x) { return 1.f/(1.f + __expf(-x)); }
__device__ __forceinline__ float tanh_fast(float x)
{
    float e = __expf(-2.f*fabsf(x));
    float t = (1.f - e)/(1.f + e);
    return copysignf(t, x);
}

// ---------------- packed f32x2 FMA helpers (sm_103a) ----------------------
__device__ __forceinline__ unsigned long long f2pack(float x, float y)
{
    unsigned long long r;
    asm("mov.b64 %0, {%1, %2};" : "=l"(r) : "f"(x), "f"(y));
    return r;
}
__device__ __forceinline__ void f2fma(unsigned long long& d,
                                      unsigned long long a, unsigned long long b)
{
    asm("fma.rn.f32x2 %0, %1, %2, %0;" : "+l"(d) : "l"(a), "l"(b));
}
__device__ __forceinline__ float f2sum(unsigned long long v)
{
    float x, y;
    asm("mov.b64 {%0, %1}, %2;" : "=f"(x), "=f"(y) : "l"(v));
    return x + y;
}
__device__ __forceinline__ void f2unpack(unsigned long long v, float& x, float& y)
{
    asm("mov.b64 {%0, %1}, %2;" : "=f"(x), "=f"(y) : "l"(v));
}

__device__ __forceinline__ unsigned smem_u32(const void* p)
{
    unsigned a;
    asm("{ .reg .u64 t; cvta.to.shared.u64 t, %1; cvt.u32.u64 %0, t; }"
        : "=r"(a) : "l"(p));
    return a;
}
__device__ __forceinline__ void st_cluster_f32(unsigned local_addr, unsigned rank, float v)
{
    unsigned remote;
    asm volatile("mapa.shared::cluster.u32 %0, %1, %2;"
                 : "=r"(remote) : "r"(local_addr), "r"(rank));
    asm volatile("st.shared::cluster.f32 [%0], %1;"
                 :: "r"(remote), "f"(v) : "memory");
}
__device__ __forceinline__ void cluster_sync_()
{
    asm volatile("barrier.cluster.arrive.aligned;" ::: "memory");
    asm volatile("barrier.cluster.wait.aligned;"   ::: "memory");
}

// ---------------- fused GAT (both layers + pool), one block per frame -----
#define OFF_XS     0          // 352
#define OFF_H1     352        // 11264 (reused as x1 after relu)
#define OFF_ASRC   11616      // 88
#define OFF_ADST   11704      // 88
#define OFF_ALPHA1 11792      // 1936
#define OFF_H2     13728      // 2816
#define OFF_A2S    16544      // 22
#define OFF_A2D    16566      // 22
#define OFF_ALPHA2 16588      // 484
#define OFF_PSUM   17072      // 256
#define GAT_SMEM_FLOATS 17328
#define GAT_SMEM_BYTES (GAT_SMEM_FLOATS*4)

extern "C" __global__ void __launch_bounds__(256, 3)
gat_kernel(const float* __restrict__ feat,
           const float* __restrict__ W1, const float* __restrict__ aS1,
           const float* __restrict__ aD1, const float* __restrict__ b1,
           const float* __restrict__ W2, const float* __restrict__ aS2,
           const float* __restrict__ aD2, const float* __restrict__ b2,
           float* __restrict__ pooled)
{
    extern __shared__ float sm[];
    float* xs     = sm + OFF_XS;
    float* h1     = sm + OFF_H1;    // later x1
    float* asrc   = sm + OFF_ASRC;
    float* adst   = sm + OFF_ADST;
    float* alpha1 = sm + OFF_ALPHA1;
    float* h2     = sm + OFF_H2;
    float* a2s    = sm + OFF_A2S;
    float* a2d    = sm + OFF_A2D;
    float* alpha2 = sm + OFF_ALPHA2;
    float* psum   = sm + OFF_PSUM;

    const int n   = blockIdx.x;
    const int tid = threadIdx.x;

    float4* h1_4 = (float4*)h1;
    const float4* W1_4 = (const float4*)W1;
    const float4* b1_4 = (const float4*)b1;

    {
        const float* xgm = feat + (long)n * (AA*FIN);
        for (int i = tid; i < AA*FIN; i += 256) xs[i] = xgm[i];
    }
    __syncthreads();

    // h1[a][hc] = x @ W1
    #pragma unroll
    for (int s = 0; s < 11; s++) {
        int o4 = tid + s*256;
        int a = o4 >> 7, c4 = o4 & 127;
        float4 acc = {0.f,0.f,0.f,0.f};
        #pragma unroll
        for (int f = 0; f < FIN; f++) {
            float xv = xs[a*FIN + f];
            float4 w = W1_4[f*128 + c4];
            acc.x += xv*w.x; acc.y += xv*w.y; acc.z += xv*w.z; acc.w += xv*w.w;
        }
        h1_4[o4] = acc;
    }
    __syncthreads();

    if (tid < 176) {
        int p = tid; bool dst = (p >= 88); if (dst) p -= 88;
        int a = p >> 2, hd = p & 3;
        const float4* att4 = (const float4*)(dst ? aD1 : aS1);
        float a0=0.f,a1=0.f,a2=0.f,a3=0.f;
        #pragma unroll 8
        for (int q = 0; q < 32; q++) {
            float4 h = h1_4[a*128 + hd*32 + q];
            float4 w = att4[hd*32 + q];
            a0 += h.x*w.x; a1 += h.y*w.y; a2 += h.z*w.z; a3 += h.w*w.w;
        }
        (dst ? adst : asrc)[a*4 + hd] = (a0+a1)+(a2+a3);
    }
    __syncthreads();

    if (tid < 88) {
        int i = tid >> 2, hd = tid & 3;
        float di = adst[i*4 + hd];
        float e[AA]; float m = -1e30f;
        #pragma unroll
        for (int j = 0; j < AA; j++) {
            float v = di + asrc[j*4 + hd];
            v = (v > 0.f) ? v : 0.2f*v;
            e[j] = v; m = fmaxf(m, v);
        }
        float ssum = 0.f;
        #pragma unroll
        for (int j = 0; j < AA; j++) { float ex = __expf(e[j]-m); e[j] = ex; ssum += ex; }
        float inv = 1.f/ssum;
        #pragma unroll
        for (int j = 0; j < AA; j++) alpha1[(i*AA+j)*4 + hd] = e[j]*inv;
    }
    __syncthreads();

    // out1 = alpha1 @ h1 — j-outer: each thread's 11 outputs share c4, a = a0+2s.
    // hv loaded ONCE per j and reused for all 11 s (alpha loads are warp-uniform).
    unsigned long long o01[11], o23[11];
    #pragma unroll
    for (int s = 0; s < 11; s++) { o01[s] = 0ull; o23[s] = 0ull; }
    {
        const int c4 = tid & 127, a0 = tid >> 7, hd = c4 >> 5;
        #pragma unroll
        for (int j = 0; j < AA; j++) {
            ulonglong2 hv = *(const ulonglong2*)&h1_4[j*128 + c4];
            #pragma unroll
            for (int s = 0; s < 11; s++) {
                float al = alpha1[((a0 + 2*s)*AA + j)*4 + hd];
                unsigned long long aa = f2pack(al, al);
                f2fma(o01[s], hv.x, aa);
                f2fma(o23[s], hv.y, aa);
            }
        }
    }
    __syncthreads();
    #pragma unroll
    for (int s = 0; s < 11; s++) {
        int o4 = tid + s*256;
        int c4 = o4 & 127;
        float4 bv = b1_4[c4];
        float vx, vy, vz, vw;
        f2unpack(o01[s], vx, vy);
        f2unpack(o23[s], vz, vw);
        float4 v;
        v.x = fmaxf(vx + bv.x, 0.f);
        v.y = fmaxf(vy + bv.y, 0.f);
        v.z = fmaxf(vz + bv.z, 0.f);
        v.w = fmaxf(vw + bv.w, 0.f);
        h1_4[o4] = v;
    }
    __syncthreads();

    // h2 = x1 @ W2 (f32x2)
    {
        int c = tid & 127, ih = tid >> 7;
        int i0 = ih * 11;
        unsigned long long acc2[11];
        #pragma unroll
        for (int ii = 0; ii < 11; ii++) acc2[ii] = 0ull;
        for (int k4 = 0; k4 < 128; k4++) {
            int k = k4*4;
            float w0 = W2[(k+0)*CC + c];
            float w1 = W2[(k+1)*CC + c];
            float w2 = W2[(k+2)*CC + c];
            float w3 = W2[(k+3)*CC + c];
            unsigned long long w01 = f2pack(w0, w1);
            unsigned long long w23 = f2pack(w2, w3);
            #pragma unroll
            for (int ii = 0; ii < 11; ii++) {
                ulonglong2 xv = *(const ulonglong2*)&h1_4[(i0+ii)*128 + k4];
                f2fma(acc2[ii], xv.x, w01);
                f2fma(acc2[ii], xv.y, w23);
            }
        }
        #pragma unroll
        for (int ii = 0; ii < 11; ii++) h2[(i0+ii)*CC + c] = f2sum(acc2[ii]);
    }
    __syncthreads();

    if (tid < 44) {
        int i = tid % AA; bool dst = (tid >= AA);
        const float4* att4 = (const float4*)(dst ? aD2 : aS2);
        const float4* h2_4 = (const float4*)h2;
        float a0=0.f,a1=0.f,a2=0.f,a3=0.f;
        #pragma unroll 8
        for (int q = 0; q < 32; q++) {
            float4 h = h2_4[i*32 + q];
            float4 w = att4[q];
            a0 += h.x*w.x; a1 += h.y*w.y; a2 += h.z*w.z; a3 += h.w*w.w;
        }
        (dst ? a2d : a2s)[i] = (a0+a1)+(a2+a3);
    }
    __syncthreads();
    if (tid < AA) {
        int i = tid;
        float di = a2d[i];
        float e[AA]; float m = -1e30f;
        #pragma unroll
        for (int j = 0; j < AA; j++) {
            float v = di + a2s[j];
            v = (v > 0.f) ? v : 0.2f*v;
            e[j] = v; m = fmaxf(m, v);
        }
        float ssum = 0.f;
        #pragma unroll
        for (int j = 0; j < AA; j++) { float ex = __expf(e[j]-m); e[j] = ex; ssum += ex; }
        float inv = 1.f/ssum;
        #pragma unroll
        for (int j = 0; j < AA; j++) alpha2[i*AA+j] = e[j]*inv;
    }
    __syncthreads();

    {
        int c = tid & 127, ih = tid >> 7;
        float bc = b2[c];
        float s = 0.f;
        for (int i = ih*11; i < ih*11 + 11; i++) {
            float acc = bc;
            #pragma unroll
            for (int j = 0; j < AA; j++) acc += alpha2[i*AA+j] * h2[j*CC + c];
            s += fmaxf(acc, 0.f);
        }
        psum[ih*128 + c] = s;
    }
    __syncthreads();
    if (tid < CC)
        pooled[(long)n*CC + tid] = (psum[tid] + psum[128 + tid]) * (1.f/22.f);
}

// ---------------- input GEMM: out[n][j] = X[n]·W[j] + bi[j] + bh[j] --------
extern "C" __global__ void __launch_bounds__(256)
gemm_xg(const float* __restrict__ X, const float* __restrict__ W,
        const float* __restrict__ bi, const float* __restrict__ bh,
        float* __restrict__ out, int K)
{
    __shared__ float xsm[16*256];
    const int n0 = blockIdx.x * 16;
    const int tid = threadIdx.x;
    for (int idx = tid; idx < 16*K; idx += 256) xsm[idx] = X[(long)n0*K + idx];
    __syncthreads();

    float acc[16][4];
    #pragma unroll
    for (int nn = 0; nn < 16; nn++)
        #pragma unroll
        for (int m = 0; m < 4; m++) acc[nn][m] = 0.f;

    const int r0 = tid, r1 = tid+256, r2 = tid+512, r3 = tid+768;
    for (int k = 0; k < K; k += 4) {
        float4 w0 = *(const float4*)&W[(long)r0*K + k];
        float4 w1 = *(const float4*)&W[(long)r1*K + k];
        float4 w2 = *(const float4*)&W[(long)r2*K + k];
        float4 w3 = *(const float4*)&W[(long)r3*K + k];
        #pragma unroll
        for (int nn = 0; nn < 16; nn++) {
            float4 xv = *(const float4*)&xsm[nn*K + k];
            acc[nn][0] += xv.x*w0.x + xv.y*w0.y + xv.z*w0.z + xv.w*w0.w;
            acc[nn][1] += xv.x*w1.x + xv.y*w1.y + xv.z*w1.z + xv.w*w1.w;
            acc[nn][2] += xv.x*w2.x + xv.y*w2.y + xv.z*w2.z + xv.w*w2.w;
            acc[nn][3] += xv.x*w3.x + xv.y*w3.y + xv.z*w3.z + xv.w*w3.w;
        }
    }
    float bsum0 = bi[r0]+bh[r0], bsum1 = bi[r1]+bh[r1], bsum2 = bi[r2]+bh[r2], bsum3 = bi[r3]+bh[r3];
    #pragma unroll
    for (int nn = 0; nn < 16; nn++) {
        long base = (long)(n0+nn)*G4;
        out[base + r0] = acc[nn][0] + bsum0;
        out[base + r1] = acc[nn][1] + bsum1;
        out[base + r2] = acc[nn][2] + bsum2;
        out[base + r3] = acc[nn][3] + bsum3;
    }
}

// ---------------- cluster-parallel 2-layer pipelined LSTM ------------------
// 8 clusters x 16 CTAs; cluster c owns batches 4c..4c+3.
// CTA rank rk owns units rk*16..rk*16+15 of BOTH layers.
// 512 threads/CTA: dots k-split across lane pairs (half = tid&1), reduced via
// shfl_xor(1) — halves the serial per-thread dot chain (latency-bound rounds).
#define CLN 16
#define LTHR 512
// smem layout (floats)
#define LOFF_WS0 0            // 64 x 260  = 16640
#define LOFF_WS1 16640        // 64 x 524  = 33536
#define LOFF_H0B 50176        // 2 x 4 x 260 = 2080
#define LOFF_H1B 52256        // 2 x 4 x 260 = 2080
#define LOFF_GS0 54336        // 4 x 64 = 256
#define LOFF_GS1 54592        // 4 x 64 = 256
#define LOFF_B1S 54848        // 64
#define LSTM_SMEM_FLOATS 54912
#define LSTM_SMEM_BYTES (LSTM_SMEM_FLOATS*4)   // 219648

extern "C" __global__ void __launch_bounds__(LTHR)
__cluster_dims__(CLN, 1, 1)
lstm_cluster(const float* __restrict__ xg0,
             const float* __restrict__ Whh0,
             const float* __restrict__ Wih1, const float* __restrict__ Whh1,
             const float* __restrict__ bih1, const float* __restrict__ bhh1,
             const int* __restrict__ slen,
             float* __restrict__ hlast)
{
    extern __shared__ float smf[];
    float* ws0 = smf + LOFF_WS0;
    float* ws1 = smf + LOFF_WS1;
    float* h0b = smf + LOFF_H0B;
    float* h1b = smf + LOFF_H1B;
    float* gs0 = smf + LOFF_GS0;
    float* gs1 = smf + LOFF_GS1;
    float* b1s = smf + LOFF_B1S;

    const int tid = threadIdx.x;
    const int cl  = blockIdx.x >> 4;     // cluster id (batch group)
    const int rk  = blockIdx.x & 15;     // rank in cluster (unit group)

    // ---- init: load weight slices ----
    for (int idx = tid; idx < 64*256; idx += LTHR) {
        int lw = idx >> 8, k = idx & 255;
        int j = (lw >> 4)*256 + rk*16 + (lw & 15);
        ws0[lw*260 + k] = Whh0[j*256 + k];
    }
    for (int idx = tid; idx < 64*512; idx += LTHR) {
        int lw = idx >> 9, k = idx & 511;
        int j = (lw >> 4)*256 + rk*16 + (lw & 15);
        ws1[lw*524 + k] = (k < 256) ? Wih1[j*256 + k] : Whh1[j*256 + (k-256)];
    }
    if (tid < 64) {
        int j = (tid >> 4)*256 + rk*16 + (tid & 15);
        b1s[tid] = bih1[j] + bhh1[j];
    }
    // zero h buffers (both parities, incl pad)
    for (int idx = tid; idx < 2*4*260; idx += LTHR) { h0b[idx] = 0.f; h1b[idx] = 0.f; }

    // dot-task mapping: tid = lr*8 + b*2 + half
    const int half = tid & 1, b = (tid >> 1) & 3, lr = tid >> 3;
    const int bg = cl*4 + b;
    const int j0 = (lr >> 4)*256 + rk*16 + (lr & 15);
    // nonlinearity mapping: tid<64 -> L0; tid in [64,128) -> L1
    const int nb = (tid < 64) ? (tid >> 4) : ((tid - 64) >> 4);
    const int nu = (tid < 64) ? (tid & 15) : ((tid - 64) & 15);
    const int nlen = read_len(slen, cl*4 + nb);
    const int uglob = rk*16 + nu;
    float creg = 0.f;

    const float4* ws0_4 = (const float4*)ws0;
    const float4* ws1_4 = (const float4*)ws1;

    float xn = (half == 0) ? xg0[(long)(bg*TT + 0)*G4 + j0] : 0.f;

    cluster_sync_();   // weights + zeroed h visible cluster-wide

    for (int r = 0; r <= TT; r++) {
        const int rp = (r + 1) & 1;   // read parity (h[r-1])
        const int wp = r & 1;         // write parity (h[r])

        // ---- L0 partial dot: k-range [half*128, half*128+128) ----
        if (r < TT) {
            const float4* h0r = (const float4*)(h0b + rp*1040 + b*260);
            unsigned long long a01 = 0ull, a23 = 0ull;
            #pragma unroll 8
            for (int k4 = 0; k4 < 32; k4++) {
                int kk = half*32 + k4;
                ulonglong2 h = *(const ulonglong2*)&h0r[kk];
                ulonglong2 w = *(const ulonglong2*)&ws0_4[lr*65 + kk];
                f2fma(a01, h.x, w.x);
                f2fma(a23, h.y, w.y);
            }
            float p = f2sum(a01) + f2sum(a23);
            p += __shfl_xor_sync(0xffffffffu, p, 1);
            if (half == 0) {
                gs0[b*64 + lr] = p + xn;
                if (r + 1 < TT) xn = xg0[(long)(bg*TT + (r+1))*G4 + j0];
            }
        }

        // ---- L1 partial dot: half 0 -> h0 part (w[0:256]), half 1 -> h1 part ----
        if (r >= 1) {
            const float4* hs4 = (const float4*)((half ? h1b : h0b) + rp*1040 + b*260);
            const int wo = half*64;
            unsigned long long a01 = 0ull, a23 = 0ull;
            #pragma unroll 8
            for (int k4 = 0; k4 < 64; k4++) {
                ulonglong2 h = *(const ulonglong2*)&hs4[k4];
                ulonglong2 w = *(const ulonglong2*)&ws1_4[lr*131 + wo + k4];
                f2fma(a01, h.x, w.x);
                f2fma(a23, h.y, w.y);
            }
            float p = f2sum(a01) + f2sum(a23);
            p += __shfl_xor_sync(0xffffffffu, p, 1);
            if (half == 0) gs1[b*64 + lr] = p + b1s[lr];
        }
        __syncthreads();

        // ---- nonlinearity + DSMEM broadcast ----
        if (tid < 64 && r < TT) {
            float gi = sig_fast (gs0[nb*64 +  0 + nu]);
            float gf = sig_fast (gs0[nb*64 + 16 + nu]);
            float gg = tanh_fast(gs0[nb*64 + 32 + nu]);
            float go = sig_fast (gs0[nb*64 + 48 + nu]);
            float cn = gf*creg + gi*gg;
            float hn = go * tanh_fast(cn);
            if (r >= nlen) { cn = creg; hn = h0b[rp*1040 + nb*260 + uglob]; }
            creg = cn;
            unsigned la = smem_u32(&h0b[wp*1040 + nb*260 + uglob]);
            #pragma unroll
            for (int d = 0; d < CLN; d++) st_cluster_f32(la, d, hn);
        } else if (tid >= 64 && tid < 128 && r >= 1) {
            const int s = r - 1;
            float gi = sig_fast (gs1[nb*64 +  0 + nu]);
            float gf = sig_fast (gs1[nb*64 + 16 + nu]);
            float gg = tanh_fast(gs1[nb*64 + 32 + nu]);
            float go = sig_fast (gs1[nb*64 + 48 + nu]);
            float cn = gf*creg + gi*gg;
            float hn = go * tanh_fast(cn);
            if (s >= nlen) { cn = creg; hn = h1b[rp*1040 + nb*260 + uglob]; }
            creg = cn;
            if (s < TT-1) {
                unsigned la = smem_u32(&h1b[wp*1040 + nb*260 + uglob]);
                #pragma unroll
                for (int d = 0; d < CLN; d++) st_cluster_f32(la, d, hn);
            } else {
                hlast[(cl*4 + nb)*HID + uglob] = hn;
            }
        }

        if (r < TT) cluster_sync_();
    }

    // final safety: no CTA exits while any peer-smem op could be in flight
    cluster_sync_();
}

extern "C" __global__ void final_kernel(const float* __restrict__ hlast,
                                        const float* __restrict__ w,
                                        const float* __restrict__ bias,
                                        float* __restrict__ out)
{
    // 256 threads: 32 batches x 8 lanes; each lane sums 32 strided elems
    const int tid = threadIdx.x;
    const int b = tid >> 3, l = tid & 7;
    float s = 0.f;
    for (int k = l; k < HID; k += 8) s += hlast[b*HID + k] * w[k];
    s += __shfl_xor_sync(0xffffffffu, s, 4);
    s += __shfl_xor_sync(0xffffffffu, s, 2);
    s += __shfl_xor_sync(0xffffffffu, s, 1);
    if (l == 0) out[b] = s + bias[0];
}

// ---------------- launch ----------------
extern "C" void kernel_launch(void* const* d_in, const int* in_sizes, int n_in,
                              void* d_out, int out_size)
{
    const float* feat = (const float*)d_in[0];
    const int*   slen = (const int*)d_in[1];
    const float* W1   = (const float*)d_in[2];
    const float* aS1  = (const float*)d_in[3];
    const float* aD1  = (const float*)d_in[4];
    const float* b1   = (const float*)d_in[5];
    const float* W2   = (const float*)d_in[6];
    const float* aS2  = (const float*)d_in[7];
    const float* aD2  = (const float*)d_in[8];
    const float* b2   = (const float*)d_in[9];
    const float* Wih0 = (const float*)d_in[10];
    const float* Whh0 = (const float*)d_in[11];
    const float* bih0 = (const float*)d_in[12];
    const float* bhh0 = (const float*)d_in[13];
    const float* Wih1 = (const float*)d_in[14];
    const float* Whh1 = (const float*)d_in[15];
    const float* bih1 = (const float*)d_in[16];
    const float* bhh1 = (const float*)d_in[17];
    const float* clfw = (const float*)d_in[18];
    const float* clfb = (const float*)d_in[19];
    float* out = (float*)d_out;

    cudaFuncSetAttribute(gat_kernel,   cudaFuncAttributeMaxDynamicSharedMemorySize, GAT_SMEM_BYTES);
    cudaFuncSetAttribute(lstm_cluster, cudaFuncAttributeMaxDynamicSharedMemorySize, LSTM_SMEM_BYTES);
    cudaFuncSetAttribute(lstm_cluster, cudaFuncAttributeNonPortableClusterSizeAllowed, 1);

    float* pooled; cudaGetSymbolAddress((void**)&pooled, g_pooled);
    float* xg;     cudaGetSymbolAddress((void**)&xg,     g_xg);
    float* hlast;  cudaGetSymbolAddress((void**)&hlast,  g_hlast);

    // 1) fused GAT + pooling over all 8192 frames
    gat_kernel<<<NF, 256, GAT_SMEM_BYTES>>>(feat, W1, aS1, aD1, b1, W2, aS2, aD2, b2, pooled);

    // 2) layer-0 input transform: xg = pooled @ Wih0^T + bih0 + bhh0
    gemm_xg<<<NF/16, 256>>>(pooled, Wih0, bih0, bhh0, xg, CC);

    // 3) cluster-parallel fused 2-layer recurrence (512 threads: k-split dots)
    lstm_cluster<<<128, LTHR, LSTM_SMEM_BYTES>>>(xg, Whh0, Wih1, Whh1, bih1, bhh1,
                                                 slen, hlast);

    // 4) classifier
    final_kernel<<<1, 256>>>(hlast, clfw, clfb, out);
}

// round 14
// speedup vs baseline: 1.0019x; 1.0019x over previous
#include <cuda_runtime.h>
#include <cuda_bf16.h>
#include <math.h>

#define BB 32
#define TT 256
#define AA 22
#define FIN 16
#define CC 128
#define HC 512
#define HID 256
#define G4 1024
#define NF (BB*TT)        // 8192 frames

// ---------------- device scratch (static allocations only) ----------------
__device__ float g_pooled[NF*CC];          // 4 MB
__device__ float g_xg[NF*G4];              // 32 MB (layer-0 input transform)
__device__ float g_hlast[BB*HID];

// dtype-robust seq_length read (JAX x64-off => int32 even though ref says int64)
__device__ __forceinline__ int read_len(const int* p, int b)
{
    bool is64 = (p[1] == 0) && (p[3] == 0);
    return is64 ? p[2*b] : p[b];
}

// fast, accurate-enough nonlinearities (errors ~1e-7, budget is 1e-3)
__device__ __forceinline__ float sig_fast(float x) { return 1.f/(1.f + __expf(-x)); }
__device__ __forceinline__ float tanh_fast(float x)
{
    float e = __expf(-2.f*fabsf(x));
    float t = (1.f - e)/(1.f + e);
    return copysignf(t, x);
}

// ---------------- packed f32x2 FMA helpers (sm_103a) ----------------------
__device__ __forceinline__ unsigned long long f2pack(float x, float y)
{
    unsigned long long r;
    asm("mov.b64 %0, {%1, %2};" : "=l"(r) : "f"(x), "f"(y));
    return r;
}
__device__ __forceinline__ void f2fma(unsigned long long& d,
                                      unsigned long long a, unsigned long long b)
{
    asm("fma.rn.f32x2 %0, %1, %2, %0;" : "+l"(d) : "l"(a), "l"(b));
}
__device__ __forceinline__ float f2sum(unsigned long long v)
{
    float x, y;
    asm("mov.b64 {%0, %1}, %2;" : "=f"(x), "=f"(y) : "l"(v));
    return x + y;
}
__device__ __forceinline__ void f2unpack(unsigned long long v, float& x, float& y)
{
    asm("mov.b64 {%0, %1}, %2;" : "=f"(x), "=f"(y) : "l"(v));
}

__device__ __forceinline__ unsigned smem_u32(const void* p)
{
    unsigned a;
    asm("{ .reg .u64 t; cvta.to.shared.u64 t, %1; cvt.u32.u64 %0, t; }"
        : "=r"(a) : "l"(p));
    return a;
}
__device__ __forceinline__ void st_cluster_f32(unsigned local_addr, unsigned rank, float v)
{
    unsigned remote;
    asm volatile("mapa.shared::cluster.u32 %0, %1, %2;"
                 : "=r"(remote) : "r"(local_addr), "r"(rank));
    asm volatile("st.shared::cluster.f32 [%0], %1;"
                 :: "r"(remote), "f"(v) : "memory");
}
__device__ __forceinline__ void cluster_sync_()
{
    asm volatile("barrier.cluster.arrive.aligned;" ::: "memory");
    asm volatile("barrier.cluster.wait.aligned;"   ::: "memory");
}

// ---------------- fused GAT (both layers + pool), one block per frame -----
#define OFF_XS     0          // 352
#define OFF_H1     352        // 11264 (reused as x1 after relu)
#define OFF_ASRC   11616      // 88
#define OFF_ADST   11704      // 88
#define OFF_ALPHA1 11792      // 1936
#define OFF_H2     13728      // 2816
#define OFF_A2S    16544      // 22
#define OFF_A2D    16566      // 22
#define OFF_ALPHA2 16588      // 484
#define OFF_PSUM   17072      // 256
#define GAT_SMEM_FLOATS 17328
#define GAT_SMEM_BYTES (GAT_SMEM_FLOATS*4)

extern "C" __global__ void __launch_bounds__(256, 3)
gat_kernel(const float* __restrict__ feat,
           const float* __restrict__ W1, const float* __restrict__ aS1,
           const float* __restrict__ aD1, const float* __restrict__ b1,
           const float* __restrict__ W2, const float* __restrict__ aS2,
           const float* __restrict__ aD2, const float* __restrict__ b2,
           float* __restrict__ pooled)
{
    extern __shared__ float sm[];
    float* xs     = sm + OFF_XS;
    float* h1     = sm + OFF_H1;    // later x1
    float* asrc   = sm + OFF_ASRC;
    float* adst   = sm + OFF_ADST;
    float* alpha1 = sm + OFF_ALPHA1;
    float* h2     = sm + OFF_H2;
    float* a2s    = sm + OFF_A2S;
    float* a2d    = sm + OFF_A2D;
    float* alpha2 = sm + OFF_ALPHA2;
    float* psum   = sm + OFF_PSUM;

    const int n   = blockIdx.x;
    const int tid = threadIdx.x;

    float4* h1_4 = (float4*)h1;
    const float4* W1_4 = (const float4*)W1;
    const float4* b1_4 = (const float4*)b1;

    {
        const float* xgm = feat + (long)n * (AA*FIN);
        for (int i = tid; i < AA*FIN; i += 256) xs[i] = xgm[i];
    }
    __syncthreads();

    // h1[a][hc] = x @ W1
    #pragma unroll
    for (int s = 0; s < 11; s++) {
        int o4 = tid + s*256;
        int a = o4 >> 7, c4 = o4 & 127;
        float4 acc = {0.f,0.f,0.f,0.f};
        #pragma unroll
        for (int f = 0; f < FIN; f++) {
            float xv = xs[a*FIN + f];
            float4 w = W1_4[f*128 + c4];
            acc.x += xv*w.x; acc.y += xv*w.y; acc.z += xv*w.z; acc.w += xv*w.w;
        }
        h1_4[o4] = acc;
    }
    __syncthreads();

    if (tid < 176) {
        int p = tid; bool dst = (p >= 88); if (dst) p -= 88;
        int a = p >> 2, hd = p & 3;
        const float4* att4 = (const float4*)(dst ? aD1 : aS1);
        float a0=0.f,a1=0.f,a2=0.f,a3=0.f;
        #pragma unroll 8
        for (int q = 0; q < 32; q++) {
            float4 h = h1_4[a*128 + hd*32 + q];
            float4 w = att4[hd*32 + q];
            a0 += h.x*w.x; a1 += h.y*w.y; a2 += h.z*w.z; a3 += h.w*w.w;
        }
        (dst ? adst : asrc)[a*4 + hd] = (a0+a1)+(a2+a3);
    }
    __syncthreads();

    if (tid < 88) {
        int i = tid >> 2, hd = tid & 3;
        float di = adst[i*4 + hd];
        float e[AA]; float m = -1e30f;
        #pragma unroll
        for (int j = 0; j < AA; j++) {
            float v = di + asrc[j*4 + hd];
            v = (v > 0.f) ? v : 0.2f*v;
            e[j] = v; m = fmaxf(m, v);
        }
        float ssum = 0.f;
        #pragma unroll
        for (int j = 0; j < AA; j++) { float ex = __expf(e[j]-m); e[j] = ex; ssum += ex; }
        float inv = 1.f/ssum;
        #pragma unroll
        for (int j = 0; j < AA; j++) alpha1[(i*AA+j)*4 + hd] = e[j]*inv;
    }
    __syncthreads();

    // out1 = alpha1 @ h1 — j-outer: each thread's 11 outputs share c4, a = a0+2s.
    // hv loaded ONCE per j and reused for all 11 s (alpha loads are warp-uniform).
    unsigned long long o01[11], o23[11];
    #pragma unroll
    for (int s = 0; s < 11; s++) { o01[s] = 0ull; o23[s] = 0ull; }
    {
        const int c4 = tid & 127, a0 = tid >> 7, hd = c4 >> 5;
        #pragma unroll
        for (int j = 0; j < AA; j++) {
            ulonglong2 hv = *(const ulonglong2*)&h1_4[j*128 + c4];
            #pragma unroll
            for (int s = 0; s < 11; s++) {
                float al = alpha1[((a0 + 2*s)*AA + j)*4 + hd];
                unsigned long long aa = f2pack(al, al);
                f2fma(o01[s], hv.x, aa);
                f2fma(o23[s], hv.y, aa);
            }
        }
    }
    __syncthreads();
    #pragma unroll
    for (int s = 0; s < 11; s++) {
        int o4 = tid + s*256;
        int c4 = o4 & 127;
        float4 bv = b1_4[c4];
        float vx, vy, vz, vw;
        f2unpack(o01[s], vx, vy);
        f2unpack(o23[s], vz, vw);
        float4 v;
        v.x = fmaxf(vx + bv.x, 0.f);
        v.y = fmaxf(vy + bv.y, 0.f);
        v.z = fmaxf(vz + bv.z, 0.f);
        v.w = fmaxf(vw + bv.w, 0.f);
        h1_4[o4] = v;
    }
    __syncthreads();

    // h2 = x1 @ W2 (f32x2)
    {
        int c = tid & 127, ih = tid >> 7;
        int i0 = ih * 11;
        unsigned long long acc2[11];
        #pragma unroll
        for (int ii = 0; ii < 11; ii++) acc2[ii] = 0ull;
        for (int k4 = 0; k4 < 128; k4++) {
            int k = k4*4;
            float w0 = W2[(k+0)*CC + c];
            float w1 = W2[(k+1)*CC + c];
            float w2 = W2[(k+2)*CC + c];
            float w3 = W2[(k+3)*CC + c];
            unsigned long long w01 = f2pack(w0, w1);
            unsigned long long w23 = f2pack(w2, w3);
            #pragma unroll
            for (int ii = 0; ii < 11; ii++) {
                ulonglong2 xv = *(const ulonglong2*)&h1_4[(i0+ii)*128 + k4];
                f2fma(acc2[ii], xv.x, w01);
                f2fma(acc2[ii], xv.y, w23);
            }
        }
        #pragma unroll
        for (int ii = 0; ii < 11; ii++) h2[(i0+ii)*CC + c] = f2sum(acc2[ii]);
    }
    __syncthreads();

    if (tid < 44) {
        int i = tid % AA; bool dst = (tid >= AA);
        const float4* att4 = (const float4*)(dst ? aD2 : aS2);
        const float4* h2_4 = (const float4*)h2;
        float a0=0.f,a1=0.f,a2=0.f,a3=0.f;
        #pragma unroll 8
        for (int q = 0; q < 32; q++) {
            float4 h = h2_4[i*32 + q];
            float4 w = att4[q];
            a0 += h.x*w.x; a1 += h.y*w.y; a2 += h.z*w.z; a3 += h.w*w.w;
        }
        (dst ? a2d : a2s)[i] = (a0+a1)+(a2+a3);
    }
    __syncthreads();
    if (tid < AA) {
        int i = tid;
        float di = a2d[i];
        float e[AA]; float m = -1e30f;
        #pragma unroll
        for (int j = 0; j < AA; j++) {
            float v = di + a2s[j];
            v = (v > 0.f) ? v : 0.2f*v;
            e[j] = v; m = fmaxf(m, v);
        }
        float ssum = 0.f;
        #pragma unroll
        for (int j = 0; j < AA; j++) { float ex = __expf(e[j]-m); e[j] = ex; ssum += ex; }
        float inv = 1.f/ssum;
        #pragma unroll
        for (int j = 0; j < AA; j++) alpha2[i*AA+j] = e[j]*inv;
    }
    __syncthreads();

    {
        int c = tid & 127, ih = tid >> 7;
        float bc = b2[c];
        float s = 0.f;
        for (int i = ih*11; i < ih*11 + 11; i++) {
            float acc = bc;
            #pragma unroll
            for (int j = 0; j < AA; j++) acc += alpha2[i*AA+j] * h2[j*CC + c];
            s += fmaxf(acc, 0.f);
        }
        psum[ih*128 + c] = s;
    }
    __syncthreads();
    if (tid < CC)
        pooled[(long)n*CC + tid] = (psum[tid] + psum[128 + tid]) * (1.f/22.f);
}

// ---------------- input GEMM: out[n][j] = X[n]·W[j] + bi[j] + bh[j] --------
extern "C" __global__ void __launch_bounds__(256)
gemm_xg(const float* __restrict__ X, const float* __restrict__ W,
        const float* __restrict__ bi, const float* __restrict__ bh,
        float* __restrict__ out, int K)
{
    __shared__ float xsm[16*256];
    const int n0 = blockIdx.x * 16;
    const int tid = threadIdx.x;
    for (int idx = tid; idx < 16*K; idx += 256) xsm[idx] = X[(long)n0*K + idx];
    __syncthreads();

    float acc[16][4];
    #pragma unroll
    for (int nn = 0; nn < 16; nn++)
        #pragma unroll
        for (int m = 0; m < 4; m++) acc[nn][m] = 0.f;

    const int r0 = tid, r1 = tid+256, r2 = tid+512, r3 = tid+768;
    for (int k = 0; k < K; k += 4) {
        float4 w0 = *(const float4*)&W[(long)r0*K + k];
        float4 w1 = *(const float4*)&W[(long)r1*K + k];
        float4 w2 = *(const float4*)&W[(long)r2*K + k];
        float4 w3 = *(const float4*)&W[(long)r3*K + k];
        #pragma unroll
        for (int nn = 0; nn < 16; nn++) {
            float4 xv = *(const float4*)&xsm[nn*K + k];
            acc[nn][0] += xv.x*w0.x + xv.y*w0.y + xv.z*w0.z + xv.w*w0.w;
            acc[nn][1] += xv.x*w1.x + xv.y*w1.y + xv.z*w1.z + xv.w*w1.w;
            acc[nn][2] += xv.x*w2.x + xv.y*w2.y + xv.z*w2.z + xv.w*w2.w;
            acc[nn][3] += xv.x*w3.x + xv.y*w3.y + xv.z*w3.z + xv.w*w3.w;
        }
    }
    float bsum0 = bi[r0]+bh[r0], bsum1 = bi[r1]+bh[r1], bsum2 = bi[r2]+bh[r2], bsum3 = bi[r3]+bh[r3];
    #pragma unroll
    for (int nn = 0; nn < 16; nn++) {
        long base = (long)(n0+nn)*G4;
        out[base + r0] = acc[nn][0] + bsum0;
        out[base + r1] = acc[nn][1] + bsum1;
        out[base + r2] = acc[nn][2] + bsum2;
        out[base + r3] = acc[nn][3] + bsum3;
    }
}

// ---------------- cluster-parallel 2-layer pipelined LSTM ------------------
// 8 clusters x 16 CTAs; cluster c owns batches 4c..4c+3.
// CTA rank rk owns units rk*16..rk*16+15 of BOTH layers.
// 512 threads/CTA: dots k-split across lane pairs (half = tid&1), reduced via
// shfl_xor(1) — halves the serial per-thread dot chain (latency-bound rounds).
#define CLN 16
#define LTHR 512
// smem layout (floats)
#define LOFF_WS0 0            // 64 x 260  = 16640
#define LOFF_WS1 16640        // 64 x 524  = 33536
#define LOFF_H0B 50176        // 2 x 4 x 260 = 2080
#define LOFF_H1B 52256        // 2 x 4 x 260 = 2080
#define LOFF_GS0 54336        // 4 x 64 = 256
#define LOFF_GS1 54592        // 4 x 64 = 256
#define LOFF_B1S 54848        // 64
#define LSTM_SMEM_FLOATS 54912
#define LSTM_SMEM_BYTES (LSTM_SMEM_FLOATS*4)   // 219648

extern "C" __global__ void __launch_bounds__(LTHR)
__cluster_dims__(CLN, 1, 1)
lstm_cluster(const float* __restrict__ xg0,
             const float* __restrict__ Whh0,
             const float* __restrict__ Wih1, const float* __restrict__ Whh1,
             const float* __restrict__ bih1, const float* __restrict__ bhh1,
             const int* __restrict__ slen,
             float* __restrict__ hlast)
{
    extern __shared__ float smf[];
    float* ws0 = smf + LOFF_WS0;
    float* ws1 = smf + LOFF_WS1;
    float* h0b = smf + LOFF_H0B;
    float* h1b = smf + LOFF_H1B;
    float* gs0 = smf + LOFF_GS0;
    float* gs1 = smf + LOFF_GS1;
    float* b1s = smf + LOFF_B1S;

    const int tid = threadIdx.x;
    const int cl  = blockIdx.x >> 4;     // cluster id (batch group)
    const int rk  = blockIdx.x & 15;     // rank in cluster (unit group)

    // ---- init: load weight slices ----
    for (int idx = tid; idx < 64*256; idx += LTHR) {
        int lw = idx >> 8, k = idx & 255;
        int j = (lw >> 4)*256 + rk*16 + (lw & 15);
        ws0[lw*260 + k] = Whh0[j*256 + k];
    }
    for (int idx = tid; idx < 64*512; idx += LTHR) {
        int lw = idx >> 9, k = idx & 511;
        int j = (lw >> 4)*256 + rk*16 + (lw & 15);
        ws1[lw*524 + k] = (k < 256) ? Wih1[j*256 + k] : Whh1[j*256 + (k-256)];
    }
    if (tid < 64) {
        int j = (tid >> 4)*256 + rk*16 + (tid & 15);
        b1s[tid] = bih1[j] + bhh1[j];
    }
    // zero h buffers (both parities, incl pad)
    for (int idx = tid; idx < 2*4*260; idx += LTHR) { h0b[idx] = 0.f; h1b[idx] = 0.f; }

    // dot-task mapping: tid = lr*8 + b*2 + half
    const int half = tid & 1, b = (tid >> 1) & 3, lr = tid >> 3;
    const int bg = cl*4 + b;
    const int j0 = (lr >> 4)*256 + rk*16 + (lr & 15);
    // nonlinearity mapping: tid<64 -> L0; tid in [64,128) -> L1
    const int nb = (tid < 64) ? (tid >> 4) : ((tid - 64) >> 4);
    const int nu = (tid < 64) ? (tid & 15) : ((tid - 64) & 15);
    const int nlen = read_len(slen, cl*4 + nb);
    const int uglob = rk*16 + nu;
    float creg = 0.f;

    const float4* ws0_4 = (const float4*)ws0;
    const float4* ws1_4 = (const float4*)ws1;

    float xn = (half == 0) ? xg0[(long)(bg*TT + 0)*G4 + j0] : 0.f;

    cluster_sync_();   // weights + zeroed h visible cluster-wide

    for (int r = 0; r <= TT; r++) {
        const int rp = (r + 1) & 1;   // read parity (h[r-1])
        const int wp = r & 1;         // write parity (h[r])

        // ---- L0 partial dot: k-range [half*128, half*128+128) ----
        if (r < TT) {
            const float4* h0r = (const float4*)(h0b + rp*1040 + b*260);
            unsigned long long a01 = 0ull, a23 = 0ull;
            #pragma unroll 8
            for (int k4 = 0; k4 < 32; k4++) {
                int kk = half*32 + k4;
                ulonglong2 h = *(const ulonglong2*)&h0r[kk];
                ulonglong2 w = *(const ulonglong2*)&ws0_4[lr*65 + kk];
                f2fma(a01, h.x, w.x);
                f2fma(a23, h.y, w.y);
            }
            float p = f2sum(a01) + f2sum(a23);
            p += __shfl_xor_sync(0xffffffffu, p, 1);
            if (half == 0) {
                gs0[b*64 + lr] = p + xn;
                if (r + 1 < TT) xn = xg0[(long)(bg*TT + (r+1))*G4 + j0];
            }
        }

        // ---- L1 partial dot: half 0 -> h0 part (w[0:256]), half 1 -> h1 part ----
        if (r >= 1) {
            const float4* hs4 = (const float4*)((half ? h1b : h0b) + rp*1040 + b*260);
            const int wo = half*64;
            unsigned long long a01 = 0ull, a23 = 0ull;
            #pragma unroll 8
            for (int k4 = 0; k4 < 64; k4++) {
                ulonglong2 h = *(const ulonglong2*)&hs4[k4];
                ulonglong2 w = *(const ulonglong2*)&ws1_4[lr*131 + wo + k4];
                f2fma(a01, h.x, w.x);
                f2fma(a23, h.y, w.y);
            }
            float p = f2sum(a01) + f2sum(a23);
            p += __shfl_xor_sync(0xffffffffu, p, 1);
            if (half == 0) gs1[b*64 + lr] = p + b1s[lr];
        }
        __syncthreads();

        // ---- nonlinearity + DSMEM broadcast ----
        if (tid < 64 && r < TT) {
            float gi = sig_fast (gs0[nb*64 +  0 + nu]);
            float gf = sig_fast (gs0[nb*64 + 16 + nu]);
            float gg = tanh_fast(gs0[nb*64 + 32 + nu]);
            float go = sig_fast (gs0[nb*64 + 48 + nu]);
            float cn = gf*creg + gi*gg;
            float hn = go * tanh_fast(cn);
            if (r >= nlen) { cn = creg; hn = h0b[rp*1040 + nb*260 + uglob]; }
            creg = cn;
            unsigned la = smem_u32(&h0b[wp*1040 + nb*260 + uglob]);
            #pragma unroll
            for (int d = 0; d < CLN; d++) st_cluster_f32(la, d, hn);
        } else if (tid >= 64 && tid < 128 && r >= 1) {
            const int s = r - 1;
            float gi = sig_fast (gs1[nb*64 +  0 + nu]);
            float gf = sig_fast (gs1[nb*64 + 16 + nu]);
            float gg = tanh_fast(gs1[nb*64 + 32 + nu]);
            float go = sig_fast (gs1[nb*64 + 48 + nu]);
            float cn = gf*creg + gi*gg;
            float hn = go * tanh_fast(cn);
            if (s >= nlen) { cn = creg; hn = h1b[rp*1040 + nb*260 + uglob]; }
            creg = cn;
            if (s < TT-1) {
                unsigned la = smem_u32(&h1b[wp*1040 + nb*260 + uglob]);
                #pragma unroll
                for (int d = 0; d < CLN; d++) st_cluster_f32(la, d, hn);
            } else {
                hlast[(cl*4 + nb)*HID + uglob] = hn;
            }
        }

        if (r < TT) cluster_sync_();
    }

    // final safety: no CTA exits while any peer-smem op could be in flight
    cluster_sync_();
}

extern "C" __global__ void final_kernel(const float* __restrict__ hlast,
                                        const float* __restrict__ w,
                                        const float* __restrict__ bias,
                                        float* __restrict__ out)
{
    // 256 threads: 32 batches x 8 lanes; each lane sums 32 strided elems
    const int tid = threadIdx.x;
    const int b = tid >> 3, l = tid & 7;
    float s = 0.f;
    for (int k = l; k < HID; k += 8) s += hlast[b*HID + k] * w[k];
    s += __shfl_xor_sync(0xffffffffu, s, 4);
    s += __shfl_xor_sync(0xffffffffu, s, 2);
    s += __shfl_xor_sync(0xffffffffu, s, 1);
    if (l == 0) out[b] = s + bias[0];
}

// ---------------- launch ----------------
extern "C" void kernel_launch(void* const* d_in, const int* in_sizes, int n_in,
                              void* d_out, int out_size)
{
    const float* feat = (const float*)d_in[0];
    const int*   slen = (const int*)d_in[1];
    const float* W1   = (const float*)d_in[2];
    const float* aS1  = (const float*)d_in[3];
    const float* aD1  = (const float*)d_in[4];
    const float* b1   = (const float*)d_in[5];
    const float* W2   = (const float*)d_in[6];
    const float* aS2  = (const float*)d_in[7];
    const float* aD2  = (const float*)d_in[8];
    const float* b2   = (const float*)d_in[9];
    const float* Wih0 = (const float*)d_in[10];
    const float* Whh0 = (const float*)d_in[11];
    const float* bih0 = (const float*)d_in[12];
    const float* bhh0 = (const float*)d_in[13];
    const float* Wih1 = (const float*)d_in[14];
    const float* Whh1 = (const float*)d_in[15];
    const float* bih1 = (const float*)d_in[16];
    const float* bhh1 = (const float*)d_in[17];
    const float* clfw = (const float*)d_in[18];
    const float* clfb = (const float*)d_in[19];
    float* out = (float*)d_out;

    cudaFuncSetAttribute(gat_kernel,   cudaFuncAttributeMaxDynamicSharedMemorySize, GAT_SMEM_BYTES);
    cudaFuncSetAttribute(lstm_cluster, cudaFuncAttributeMaxDynamicSharedMemorySize, LSTM_SMEM_BYTES);
    cudaFuncSetAttribute(lstm_cluster, cudaFuncAttributeNonPortableClusterSizeAllowed, 1);

    float* pooled; cudaGetSymbolAddress((void**)&pooled, g_pooled);
    float* xg;     cudaGetSymbolAddress((void**)&xg,     g_xg);
    float* hlast;  cudaGetSymbolAddress((void**)&hlast,  g_hlast);

    // 1) fused GAT + pooling over all 8192 frames
    gat_kernel<<<NF, 256, GAT_SMEM_BYTES>>>(feat, W1, aS1, aD1, b1, W2, aS2, aD2, b2, pooled);

    // 2) layer-0 input transform: xg = pooled @ Wih0^T + bih0 + bhh0
    gemm_xg<<<NF/16, 256>>>(pooled, Wih0, bih0, bhh0, xg, CC);

    // 3) cluster-parallel fused 2-layer recurrence (512 threads: k-split dots)
    lstm_cluster<<<128, LTHR, LSTM_SMEM_BYTES>>>(xg, Whh0, Wih1, Whh1, bih1, bhh1,
                                                 slen, hlast);

    // 4) classifier
    final_kernel<<<1, 256>>>(hlast, clfw, clfb, out);
}

// round 15
// speedup vs baseline: 1.3069x; 1.3044x over previous
#include <cuda_runtime.h>
#include <cuda_bf16.h>
#include <math.h>

#define BB 32
#define TT 256
#define AA 22
#define FIN 16
#define CC 128
#define HC 512
#define HID 256
#define G4 1024
#define NF (BB*TT)        // 8192 frames

// ---------------- device scratch (static allocations only) ----------------
__device__ float g_pooled[NF*CC];          // 4 MB
__device__ float g_xg[NF*G4];              // 32 MB (layer-0 input transform)
__device__ float g_hlast[BB*HID];

// dtype-robust seq_length read (JAX x64-off => int32 even though ref says int64)
__device__ __forceinline__ int read_len(const int* p, int b)
{
    bool is64 = (p[1] == 0) && (p[3] == 0);
    return is64 ? p[2*b] : p[b];
}

// fast nonlinearities on the serial gate path (error ~1e-7, budget 1e-3)
__device__ __forceinline__ float sig_fast(float x) { return 1.f/(1.f + __expf(-x)); }
__device__ __forceinline__ float tanh_fast(float x)
{
    float e = __expf(-2.f*fabsf(x));
    float t = (1.f - e)/(1.f + e);
    return copysignf(t, x);
}

// ---------------- packed f32x2 FMA helpers (sm_103a) ----------------------
__device__ __forceinline__ unsigned long long f2pack(float x, float y)
{
    unsigned long long r;
    asm("mov.b64 %0, {%1, %2};" : "=l"(r) : "f"(x), "f"(y));
    return r;
}
__device__ __forceinline__ void f2fma(unsigned long long& d,
                                      unsigned long long a, unsigned long long b)
{
    asm("fma.rn.f32x2 %0, %1, %2, %0;" : "+l"(d) : "l"(a), "l"(b));
}
__device__ __forceinline__ float f2sum(unsigned long long v)
{
    float x, y;
    asm("mov.b64 {%0, %1}, %2;" : "=f"(x), "=f"(y) : "l"(v));
    return x + y;
}
__device__ __forceinline__ void f2unpack(unsigned long long v, float& x, float& y)
{
    asm("mov.b64 {%0, %1}, %2;" : "=f"(x), "=f"(y) : "l"(v));
}

__device__ __forceinline__ unsigned smem_u32(const void* p)
{
    unsigned a;
    asm("{ .reg .u64 t; cvta.to.shared.u64 t, %1; cvt.u32.u64 %0, t; }"
        : "=r"(a) : "l"(p));
    return a;
}
__device__ __forceinline__ void st_cluster_f32(unsigned local_addr, unsigned rank, float v)
{
    unsigned remote;
    asm volatile("mapa.shared::cluster.u32 %0, %1, %2;"
                 : "=r"(remote) : "r"(local_addr), "r"(rank));
    asm volatile("st.shared::cluster.f32 [%0], %1;"
                 :: "r"(remote), "f"(v) : "memory");
}
__device__ __forceinline__ void cluster_sync_()
{
    asm volatile("barrier.cluster.arrive.aligned;" ::: "memory");
    asm volatile("barrier.cluster.wait.aligned;"   ::: "memory");
}

// ---------------- fused GAT (both layers + pool), one block per frame -----
#define OFF_XS     0          // 352
#define OFF_H1     352        // 11264 (reused as x1 after relu)
#define OFF_ASRC   11616      // 88
#define OFF_ADST   11704      // 88
#define OFF_ALPHA1 11792      // 1936
#define OFF_H2     13728      // 2816
#define OFF_A2S    16544      // 22
#define OFF_A2D    16566      // 22
#define OFF_ALPHA2 16588      // 484
#define OFF_PSUM   17072      // 256
#define GAT_SMEM_FLOATS 17328
#define GAT_SMEM_BYTES (GAT_SMEM_FLOATS*4)

extern "C" __global__ void __launch_bounds__(256, 3)
gat_kernel(const float* __restrict__ feat,
           const float* __restrict__ W1, const float* __restrict__ aS1,
           const float* __restrict__ aD1, const float* __restrict__ b1,
           const float* __restrict__ W2, const float* __restrict__ aS2,
           const float* __restrict__ aD2, const float* __restrict__ b2,
           float* __restrict__ pooled)
{
    extern __shared__ float sm[];
    float* xs     = sm + OFF_XS;
    float* h1     = sm + OFF_H1;    // later x1
    float* asrc   = sm + OFF_ASRC;
    float* adst   = sm + OFF_ADST;
    float* alpha1 = sm + OFF_ALPHA1;
    float* h2     = sm + OFF_H2;
    float* a2s    = sm + OFF_A2S;
    float* a2d    = sm + OFF_A2D;
    float* alpha2 = sm + OFF_ALPHA2;
    float* psum   = sm + OFF_PSUM;

    const int n   = blockIdx.x;
    const int tid = threadIdx.x;

    float4* h1_4 = (float4*)h1;
    const float4* W1_4 = (const float4*)W1;
    const float4* b1_4 = (const float4*)b1;

    {
        const float* xgm = feat + (long)n * (AA*FIN);
        for (int i = tid; i < AA*FIN; i += 256) xs[i] = xgm[i];
    }
    __syncthreads();

    // h1[a][hc] = x @ W1
    #pragma unroll
    for (int s = 0; s < 11; s++) {
        int o4 = tid + s*256;
        int a = o4 >> 7, c4 = o4 & 127;
        float4 acc = {0.f,0.f,0.f,0.f};
        #pragma unroll
        for (int f = 0; f < FIN; f++) {
            float xv = xs[a*FIN + f];
            float4 w = W1_4[f*128 + c4];
            acc.x += xv*w.x; acc.y += xv*w.y; acc.z += xv*w.z; acc.w += xv*w.w;
        }
        h1_4[o4] = acc;
    }
    __syncthreads();

    if (tid < 176) {
        int p = tid; bool dst = (p >= 88); if (dst) p -= 88;
        int a = p >> 2, hd = p & 3;
        const float4* att4 = (const float4*)(dst ? aD1 : aS1);
        float a0=0.f,a1=0.f,a2=0.f,a3=0.f;
        #pragma unroll 8
        for (int q = 0; q < 32; q++) {
            float4 h = h1_4[a*128 + hd*32 + q];
            float4 w = att4[hd*32 + q];
            a0 += h.x*w.x; a1 += h.y*w.y; a2 += h.z*w.z; a3 += h.w*w.w;
        }
        (dst ? adst : asrc)[a*4 + hd] = (a0+a1)+(a2+a3);
    }
    __syncthreads();

    if (tid < 88) {
        int i = tid >> 2, hd = tid & 3;
        float di = adst[i*4 + hd];
        float e[AA]; float m = -1e30f;
        #pragma unroll
        for (int j = 0; j < AA; j++) {
            float v = di + asrc[j*4 + hd];
            v = (v > 0.f) ? v : 0.2f*v;
            e[j] = v; m = fmaxf(m, v);
        }
        float ssum = 0.f;
        #pragma unroll
        for (int j = 0; j < AA; j++) { float ex = __expf(e[j]-m); e[j] = ex; ssum += ex; }
        float inv = 1.f/ssum;
        #pragma unroll
        for (int j = 0; j < AA; j++) alpha1[(i*AA+j)*4 + hd] = e[j]*inv;
    }
    __syncthreads();

    // out1 = alpha1 @ h1 (f32x2)
    unsigned long long o01[11], o23[11];
    #pragma unroll
    for (int s = 0; s < 11; s++) { o01[s] = 0ull; o23[s] = 0ull; }
    #pragma unroll
    for (int s = 0; s < 11; s++) {
        int o4 = tid + s*256;
        int a = o4 >> 7, c4 = o4 & 127, hd = c4 >> 5;
        #pragma unroll
        for (int j = 0; j < AA; j++) {
            float al = alpha1[(a*AA+j)*4 + hd];
            unsigned long long aa = f2pack(al, al);
            ulonglong2 hv = *(const ulonglong2*)&h1_4[j*128 + c4];
            f2fma(o01[s], hv.x, aa);
            f2fma(o23[s], hv.y, aa);
        }
    }
    __syncthreads();
    #pragma unroll
    for (int s = 0; s < 11; s++) {
        int o4 = tid + s*256;
        int c4 = o4 & 127;
        float4 bv = b1_4[c4];
        float vx, vy, vz, vw;
        f2unpack(o01[s], vx, vy);
        f2unpack(o23[s], vz, vw);
        float4 v;
        v.x = fmaxf(vx + bv.x, 0.f);
        v.y = fmaxf(vy + bv.y, 0.f);
        v.z = fmaxf(vz + bv.z, 0.f);
        v.w = fmaxf(vw + bv.w, 0.f);
        h1_4[o4] = v;
    }
    __syncthreads();

    // h2 = x1 @ W2 (f32x2)
    {
        int c = tid & 127, ih = tid >> 7;
        int i0 = ih * 11;
        unsigned long long acc2[11];
        #pragma unroll
        for (int ii = 0; ii < 11; ii++) acc2[ii] = 0ull;
        for (int k4 = 0; k4 < 128; k4++) {
            int k = k4*4;
            float w0 = W2[(k+0)*CC + c];
            float w1 = W2[(k+1)*CC + c];
            float w2 = W2[(k+2)*CC + c];
            float w3 = W2[(k+3)*CC + c];
            unsigned long long w01 = f2pack(w0, w1);
            unsigned long long w23 = f2pack(w2, w3);
            #pragma unroll
            for (int ii = 0; ii < 11; ii++) {
                ulonglong2 xv = *(const ulonglong2*)&h1_4[(i0+ii)*128 + k4];
                f2fma(acc2[ii], xv.x, w01);
                f2fma(acc2[ii], xv.y, w23);
            }
        }
        #pragma unroll
        for (int ii = 0; ii < 11; ii++) h2[(i0+ii)*CC + c] = f2sum(acc2[ii]);
    }
    __syncthreads();

    if (tid < 44) {
        int i = tid % AA; bool dst = (tid >= AA);
        const float4* att4 = (const float4*)(dst ? aD2 : aS2);
        const float4* h2_4 = (const float4*)h2;
        float a0=0.f,a1=0.f,a2=0.f,a3=0.f;
        #pragma unroll 8
        for (int q = 0; q < 32; q++) {
            float4 h = h2_4[i*32 + q];
            float4 w = att4[q];
            a0 += h.x*w.x; a1 += h.y*w.y; a2 += h.z*w.z; a3 += h.w*w.w;
        }
        (dst ? a2d : a2s)[i] = (a0+a1)+(a2+a3);
    }
    __syncthreads();
    if (tid < AA) {
        int i = tid;
        float di = a2d[i];
        float e[AA]; float m = -1e30f;
        #pragma unroll
        for (int j = 0; j < AA; j++) {
            float v = di + a2s[j];
            v = (v > 0.f) ? v : 0.2f*v;
            e[j] = v; m = fmaxf(m, v);
        }
        float ssum = 0.f;
        #pragma unroll
        for (int j = 0; j < AA; j++) { float ex = __expf(e[j]-m); e[j] = ex; ssum += ex; }
        float inv = 1.f/ssum;
        #pragma unroll
        for (int j = 0; j < AA; j++) alpha2[i*AA+j] = e[j]*inv;
    }
    __syncthreads();

    {
        int c = tid & 127, ih = tid >> 7;
        float bc = b2[c];
        float s = 0.f;
        for (int i = ih*11; i < ih*11 + 11; i++) {
            float acc = bc;
            #pragma unroll
            for (int j = 0; j < AA; j++) acc += alpha2[i*AA+j] * h2[j*CC + c];
            s += fmaxf(acc, 0.f);
        }
        psum[ih*128 + c] = s;
    }
    __syncthreads();
    if (tid < CC)
        pooled[(long)n*CC + tid] = (psum[tid] + psum[128 + tid]) * (1.f/22.f);
}

// ---------------- input GEMM: out[n][j] = X[n]·W[j] + bi[j] + bh[j] --------
extern "C" __global__ void __launch_bounds__(256)
gemm_xg(const float* __restrict__ X, const float* __restrict__ W,
        const float* __restrict__ bi, const float* __restrict__ bh,
        float* __restrict__ out, int K)
{
    __shared__ float xsm[16*256];
    const int n0 = blockIdx.x * 16;
    const int tid = threadIdx.x;
    for (int idx = tid; idx < 16*K; idx += 256) xsm[idx] = X[(long)n0*K + idx];
    __syncthreads();

    float acc[16][4];
    #pragma unroll
    for (int nn = 0; nn < 16; nn++)
        #pragma unroll
        for (int m = 0; m < 4; m++) acc[nn][m] = 0.f;

    const int r0 = tid, r1 = tid+256, r2 = tid+512, r3 = tid+768;
    for (int k = 0; k < K; k += 4) {
        float4 w0 = *(const float4*)&W[(long)r0*K + k];
        float4 w1 = *(const float4*)&W[(long)r1*K + k];
        float4 w2 = *(const float4*)&W[(long)r2*K + k];
        float4 w3 = *(const float4*)&W[(long)r3*K + k];
        #pragma unroll
        for (int nn = 0; nn < 16; nn++) {
            float4 xv = *(const float4*)&xsm[nn*K + k];
            acc[nn][0] += xv.x*w0.x + xv.y*w0.y + xv.z*w0.z + xv.w*w0.w;
            acc[nn][1] += xv.x*w1.x + xv.y*w1.y + xv.z*w1.z + xv.w*w1.w;
            acc[nn][2] += xv.x*w2.x + xv.y*w2.y + xv.z*w2.z + xv.w*w2.w;
            acc[nn][3] += xv.x*w3.x + xv.y*w3.y + xv.z*w3.z + xv.w*w3.w;
        }
    }
    float bsum0 = bi[r0]+bh[r0], bsum1 = bi[r1]+bh[r1], bsum2 = bi[r2]+bh[r2], bsum3 = bi[r3]+bh[r3];
    #pragma unroll
    for (int nn = 0; nn < 16; nn++) {
        long base = (long)(n0+nn)*G4;
        out[base + r0] = acc[nn][0] + bsum0;
        out[base + r1] = acc[nn][1] + bsum1;
        out[base + r2] = acc[nn][2] + bsum2;
        out[base + r3] = acc[nn][3] + bsum3;
    }
}

// ---------------- cluster-parallel 2-layer pipelined LSTM ------------------
// 8 clusters x 16 CTAs; cluster c owns batches 4c..4c+3.
// CTA rank rk owns units rk*16..rk*16+15 of BOTH layers.
// (R9 mapping exactly: thread = (row lr, batch b); the 4 same-row lanes are
// warp-broadcast on weight reads — no redundancy penalty.)
#define CLN 16
// smem layout (floats)
#define LOFF_WS0 0            // 64 x 260  = 16640
#define LOFF_WS1 16640        // 64 x 524  = 33536
#define LOFF_H0B 50176        // 2 x 4 x 260 = 2080
#define LOFF_H1B 52256        // 2 x 4 x 260 = 2080
#define LOFF_GS0 54336        // 4 x 64 = 256
#define LOFF_GS1 54592        // 4 x 64 = 256
#define LOFF_B1S 54848        // 64
#define LSTM_SMEM_FLOATS 54912
#define LSTM_SMEM_BYTES (LSTM_SMEM_FLOATS*4)   // 219648

extern "C" __global__ void __launch_bounds__(256)
__cluster_dims__(CLN, 1, 1)
lstm_cluster(const float* __restrict__ xg0,
             const float* __restrict__ Whh0,
             const float* __restrict__ Wih1, const float* __restrict__ Whh1,
             const float* __restrict__ bih1, const float* __restrict__ bhh1,
             const int* __restrict__ slen,
             float* __restrict__ hlast)
{
    extern __shared__ float smf[];
    float* ws0 = smf + LOFF_WS0;
    float* ws1 = smf + LOFF_WS1;
    float* h0b = smf + LOFF_H0B;
    float* h1b = smf + LOFF_H1B;
    float* gs0 = smf + LOFF_GS0;
    float* gs1 = smf + LOFF_GS1;
    float* b1s = smf + LOFF_B1S;

    const int tid = threadIdx.x;
    const int cl  = blockIdx.x >> 4;     // cluster id (batch group)
    const int rk  = blockIdx.x & 15;     // rank in cluster (unit group)

    // ---- init: load weight slices ----
    for (int idx = tid; idx < 64*256; idx += 256) {
        int lw = idx >> 8, k = idx & 255;
        int j = (lw >> 4)*256 + rk*16 + (lw & 15);
        ws0[lw*260 + k] = Whh0[j*256 + k];
    }
    for (int idx = tid; idx < 64*512; idx += 256) {
        int lw = idx >> 9, k = idx & 511;
        int j = (lw >> 4)*256 + rk*16 + (lw & 15);
        ws1[lw*524 + k] = (k < 256) ? Wih1[j*256 + k] : Whh1[j*256 + (k-256)];
    }
    if (tid < 64) {
        int j = (tid >> 4)*256 + rk*16 + (tid & 15);
        b1s[tid] = bih1[j] + bhh1[j];
    }
    // zero h buffers (both parities, incl pad)
    for (int idx = tid; idx < 2*4*260; idx += 256) { h0b[idx] = 0.f; h1b[idx] = 0.f; }

    // dot-task mapping: tid = lr*4 + b
    const int lr = tid >> 2, b = tid & 3;
    const int bg = cl*4 + b;
    const int j0 = (lr >> 4)*256 + rk*16 + (lr & 15);
    // nonlinearity mapping: tid<64 -> L0; tid in [64,128) -> L1
    const int nb = (tid < 64) ? (tid >> 4) : ((tid - 64) >> 4);
    const int nu = (tid < 64) ? (tid & 15) : ((tid - 64) & 15);
    const int nlen = read_len(slen, cl*4 + nb);
    const int uglob = rk*16 + nu;
    float creg = 0.f;

    const float4* ws0_4 = (const float4*)ws0;
    const float4* ws1_4 = (const float4*)ws1;

    float xn = xg0[(long)(bg*TT + 0)*G4 + j0];   // prefetch round-0 x-gate

    cluster_sync_();   // weights + zeroed h visible cluster-wide

    for (int r = 0; r <= TT; r++) {
        const int rp = (r + 1) & 1;   // read parity (h[r-1])
        const int wp = r & 1;         // write parity (h[r])

        // ---- L0 dot: g0 = Whh0_row . h0[r-1] + xg ----
        if (r < TT) {
            const float4* h0r = (const float4*)(h0b + rp*1040 + b*260);
            unsigned long long a01 = 0ull, a23 = 0ull;
            #pragma unroll 8
            for (int k4 = 0; k4 < 64; k4++) {
                ulonglong2 h = *(const ulonglong2*)&h0r[k4];
                ulonglong2 w = *(const ulonglong2*)&ws0_4[lr*65 + k4];
                f2fma(a01, h.x, w.x);
                f2fma(a23, h.y, w.y);
            }
            gs0[b*64 + lr] = f2sum(a01) + f2sum(a23) + xn;
            if (r + 1 < TT) xn = xg0[(long)(bg*TT + (r+1))*G4 + j0];
        }

        // ---- L1 dot: g1 = W1_row . [h0[r-1] | h1[r-2]] + bias ----
        if (r >= 1) {
            const float4* h0r = (const float4*)(h0b + rp*1040 + b*260);
            const float4* h1r = (const float4*)(h1b + rp*1040 + b*260);
            unsigned long long a01 = 0ull, a23 = 0ull;
            #pragma unroll 8
            for (int k4 = 0; k4 < 64; k4++) {
                ulonglong2 x = *(const ulonglong2*)&h0r[k4];
                ulonglong2 w = *(const ulonglong2*)&ws1_4[lr*131 + k4];
                f2fma(a01, x.x, w.x);
                f2fma(a23, x.y, w.y);
            }
            #pragma unroll 8
            for (int k4 = 0; k4 < 64; k4++) {
                ulonglong2 x = *(const ulonglong2*)&h1r[k4];
                ulonglong2 w = *(const ulonglong2*)&ws1_4[lr*131 + 64 + k4];
                f2fma(a01, x.x, w.x);
                f2fma(a23, x.y, w.y);
            }
            gs1[b*64 + lr] = f2sum(a01) + f2sum(a23) + b1s[lr];
        }
        __syncthreads();

        // ---- nonlinearity + DSMEM broadcast ----
        if (tid < 64 && r < TT) {
            float gi = sig_fast (gs0[nb*64 +  0 + nu]);
            float gf = sig_fast (gs0[nb*64 + 16 + nu]);
            float gg = tanh_fast(gs0[nb*64 + 32 + nu]);
            float go = sig_fast (gs0[nb*64 + 48 + nu]);
            float cn = gf*creg + gi*gg;
            float hn = go * tanh_fast(cn);
            if (r >= nlen) { cn = creg; hn = h0b[rp*1040 + nb*260 + uglob]; }
            creg = cn;
            unsigned la = smem_u32(&h0b[wp*1040 + nb*260 + uglob]);
            #pragma unroll
            for (int d = 0; d < CLN; d++) st_cluster_f32(la, d, hn);
        } else if (tid >= 64 && tid < 128 && r >= 1) {
            const int s = r - 1;
            float gi = sig_fast (gs1[nb*64 +  0 + nu]);
            float gf = sig_fast (gs1[nb*64 + 16 + nu]);
            float gg = tanh_fast(gs1[nb*64 + 32 + nu]);
            float go = sig_fast (gs1[nb*64 + 48 + nu]);
            float cn = gf*creg + gi*gg;
            float hn = go * tanh_fast(cn);
            if (s >= nlen) { cn = creg; hn = h1b[rp*1040 + nb*260 + uglob]; }
            creg = cn;
            if (s < TT-1) {
                unsigned la = smem_u32(&h1b[wp*1040 + nb*260 + uglob]);
                #pragma unroll
                for (int d = 0; d < CLN; d++) st_cluster_f32(la, d, hn);
            } else {
                hlast[(cl*4 + nb)*HID + uglob] = hn;
            }
        }

        if (r < TT) cluster_sync_();
    }

    // final safety: no CTA exits while any peer-smem op could be in flight
    cluster_sync_();
}

extern "C" __global__ void final_kernel(const float* __restrict__ hlast,
                                        const float* __restrict__ w,
                                        const float* __restrict__ bias,
                                        float* __restrict__ out)
{
    // 256 threads: 32 batches x 8 lanes; each lane sums 32 strided elems
    const int tid = threadIdx.x;
    const int b = tid >> 3, l = tid & 7;
    float s = 0.f;
    for (int k = l; k < HID; k += 8) s += hlast[b*HID + k] * w[k];
    s += __shfl_xor_sync(0xffffffffu, s, 4);
    s += __shfl_xor_sync(0xffffffffu, s, 2);
    s += __shfl_xor_sync(0xffffffffu, s, 1);
    if (l == 0) out[b] = s + bias[0];
}

// ---------------- launch ----------------
extern "C" void kernel_launch(void* const* d_in, const int* in_sizes, int n_in,
                              void* d_out, int out_size)
{
    const float* feat = (const float*)d_in[0];
    const int*   slen = (const int*)d_in[1];
    const float* W1   = (const float*)d_in[2];
    const float* aS1  = (const float*)d_in[3];
    const float* aD1  = (const float*)d_in[4];
    const float* b1   = (const float*)d_in[5];
    const float* W2   = (const float*)d_in[6];
    const float* aS2  = (const float*)d_in[7];
    const float* aD2  = (const float*)d_in[8];
    const float* b2   = (const float*)d_in[9];
    const float* Wih0 = (const float*)d_in[10];
    const float* Whh0 = (const float*)d_in[11];
    const float* bih0 = (const float*)d_in[12];
    const float* bhh0 = (const float*)d_in[13];
    const float* Wih1 = (const float*)d_in[14];
    const float* Whh1 = (const float*)d_in[15];
    const float* bih1 = (const float*)d_in[16];
    const float* bhh1 = (const float*)d_in[17];
    const float* clfw = (const float*)d_in[18];
    const float* clfb = (const float*)d_in[19];
    float* out = (float*)d_out;

    cudaFuncSetAttribute(gat_kernel,   cudaFuncAttributeMaxDynamicSharedMemorySize, GAT_SMEM_BYTES);
    cudaFuncSetAttribute(lstm_cluster, cudaFuncAttributeMaxDynamicSharedMemorySize, LSTM_SMEM_BYTES);
    cudaFuncSetAttribute(lstm_cluster, cudaFuncAttributeNonPortableClusterSizeAllowed, 1);

    float* pooled; cudaGetSymbolAddress((void**)&pooled, g_pooled);
    float* xg;     cudaGetSymbolAddress((void**)&xg,     g_xg);
    float* hlast;  cudaGetSymbolAddress((void**)&hlast,  g_hlast);

    // 1) fused GAT + pooling over all 8192 frames
    gat_kernel<<<NF, 256, GAT_SMEM_BYTES>>>(feat, W1, aS1, aD1, b1, W2, aS2, aD2, b2, pooled);

    // 2) layer-0 input transform: xg = pooled @ Wih0^T + bih0 + bhh0
    gemm_xg<<<NF/16, 256>>>(pooled, Wih0, bih0, bhh0, xg, CC);

    // 3) cluster-parallel fused 2-layer recurrence (R9 config + fast nonlin)
    lstm_cluster<<<128, 256, LSTM_SMEM_BYTES>>>(xg, Whh0, Wih1, Whh1, bih1, bhh1,
                                                slen, hlast);

    // 4) classifier
    final_kernel<<<1, 256>>>(hlast, clfw, clfb, out);
}

// round 17
// speedup vs baseline: 1.4323x; 1.0960x over previous
#include <cuda_runtime.h>
#include <cuda_bf16.h>
#include <math.h>

#define BB 32
#define TT 256
#define AA 22
#define FIN 16
#define CC 128
#define HC 512
#define HID 256
#define G4 1024
#define NF (BB*TT)        // 8192 frames
#define LSTM_BLOCKS 128
#define PROD_BLOCKS 168
#define GRID_TOTAL (LSTM_BLOCKS + PROD_BLOCKS)   // 296 = 148*2
#define QITEMS (TT*34)    // per t: 32 gat frames + 2 gemm0 halves

// ---------------- device scratch (static allocations only) ----------------
__device__ float g_pooled[NF*CC];          // 4 MB
__device__ float g_xg0[NF*G4];             // 32 MB
__device__ float g_xg1[NF*G4];             // 32 MB
__device__ float g_h0seq[BB*TT*HID];       // 8 MB
__device__ float g_h0buf[2*BB*HID];
__device__ float g_h1buf[2*BB*HID];
__device__ float g_hlast[BB*HID];
// sync state (zeroed every launch)
__device__ unsigned g_bar_count;
__device__ volatile unsigned g_bar_epoch;
__device__ unsigned g_prodctr;
__device__ unsigned g_m1ctr;
__device__ volatile unsigned g_h0done;
__device__ unsigned g_gatdone[TT];
__device__ unsigned g_xg0ready[TT];
__device__ unsigned g_xg1ready[TT];

__device__ __forceinline__ int read_len(const int* p, int b)
{
    bool is64 = (p[1] == 0) && (p[3] == 0);
    return is64 ? p[2*b] : p[b];
}

__device__ __forceinline__ float sig_fast(float x) { return 1.f/(1.f + __expf(-x)); }
__device__ __forceinline__ float tanh_fast(float x)
{
    float e = __expf(-2.f*fabsf(x));
    float t = (1.f - e)/(1.f + e);
    return copysignf(t, x);
}

__device__ __forceinline__ unsigned long long f2pack(float x, float y)
{
    unsigned long long r;
    asm("mov.b64 %0, {%1, %2};" : "=l"(r) : "f"(x), "f"(y));
    return r;
}
__device__ __forceinline__ void f2fma(unsigned long long& d,
                                      unsigned long long a, unsigned long long b)
{
    asm("fma.rn.f32x2 %0, %1, %2, %0;" : "+l"(d) : "l"(a), "l"(b));
}
__device__ __forceinline__ float f2sum(unsigned long long v)
{
    float x, y;
    asm("mov.b64 {%0, %1}, %2;" : "=f"(x), "=f"(y) : "l"(v));
    return x + y;
}
__device__ __forceinline__ void f2unpack(unsigned long long v, float& x, float& y)
{
    asm("mov.b64 {%0, %1}, %2;" : "=f"(x), "=f"(y) : "l"(v));
}

// ---------------- GAT smem layout (floats) --------------------------------
#define OFF_XS     0
#define OFF_H1     352
#define OFF_ASRC   11616
#define OFF_ADST   11704
#define OFF_ALPHA1 11792
#define OFF_H2     13728
#define OFF_A2S    16544
#define OFF_A2D    16566
#define OFF_ALPHA2 16588
#define OFF_PSUM   17072
#define MEGA_SMEM_FLOATS 17328
#define MEGA_SMEM_BYTES (MEGA_SMEM_FLOATS*4)   // 69312

// ---------------- fused GAT for one frame (proven body) --------------------
__device__ void gat_frame(int n, float* sm, int tid,
                          const float* __restrict__ feat,
                          const float* __restrict__ W1, const float* __restrict__ aS1,
                          const float* __restrict__ aD1, const float* __restrict__ b1,
                          const float* __restrict__ W2, const float* __restrict__ aS2,
                          const float* __restrict__ aD2, const float* __restrict__ b2,
                          float* __restrict__ pooled)
{
    float* xs     = sm + OFF_XS;
    float* h1     = sm + OFF_H1;
    float* asrc   = sm + OFF_ASRC;
    float* adst   = sm + OFF_ADST;
    float* alpha1 = sm + OFF_ALPHA1;
    float* h2     = sm + OFF_H2;
    float* a2s    = sm + OFF_A2S;
    float* a2d    = sm + OFF_A2D;
    float* alpha2 = sm + OFF_ALPHA2;
    float* psum   = sm + OFF_PSUM;

    float4* h1_4 = (float4*)h1;
    const float4* W1_4 = (const float4*)W1;
    const float4* b1_4 = (const float4*)b1;

    __syncthreads();
    {
        const float* xgm = feat + (long)n * (AA*FIN);
        for (int i = tid; i < AA*FIN; i += 256) xs[i] = xgm[i];
    }
    __syncthreads();

    #pragma unroll
    for (int s = 0; s < 11; s++) {
        int o4 = tid + s*256;
        int a = o4 >> 7, c4 = o4 & 127;
        float4 acc = {0.f,0.f,0.f,0.f};
        #pragma unroll
        for (int f = 0; f < FIN; f++) {
            float xv = xs[a*FIN + f];
            float4 w = W1_4[f*128 + c4];
            acc.x += xv*w.x; acc.y += xv*w.y; acc.z += xv*w.z; acc.w += xv*w.w;
        }
        h1_4[o4] = acc;
    }
    __syncthreads();

    if (tid < 176) {
        int p = tid; bool dst = (p >= 88); if (dst) p -= 88;
        int a = p >> 2, hd = p & 3;
        const float4* att4 = (const float4*)(dst ? aD1 : aS1);
        float a0=0.f,a1=0.f,a2=0.f,a3=0.f;
        #pragma unroll 8
        for (int q = 0; q < 32; q++) {
            float4 h = h1_4[a*128 + hd*32 + q];
            float4 w = att4[hd*32 + q];
            a0 += h.x*w.x; a1 += h.y*w.y; a2 += h.z*w.z; a3 += h.w*w.w;
        }
        (dst ? adst : asrc)[a*4 + hd] = (a0+a1)+(a2+a3);
    }
    __syncthreads();

    if (tid < 88) {
        int i = tid >> 2, hd = tid & 3;
        float di = adst[i*4 + hd];
        float e[AA]; float m = -1e30f;
        #pragma unroll
        for (int j = 0; j < AA; j++) {
            float v = di + asrc[j*4 + hd];
            v = (v > 0.f) ? v : 0.2f*v;
            e[j] = v; m = fmaxf(m, v);
        }
        float ssum = 0.f;
        #pragma unroll
        for (int j = 0; j < AA; j++) { float ex = __expf(e[j]-m); e[j] = ex; ssum += ex; }
        float inv = 1.f/ssum;
        #pragma unroll
        for (int j = 0; j < AA; j++) alpha1[(i*AA+j)*4 + hd] = e[j]*inv;
    }
    __syncthreads();

    unsigned long long o01[11], o23[11];
    #pragma unroll
    for (int s = 0; s < 11; s++) { o01[s] = 0ull; o23[s] = 0ull; }
    #pragma unroll
    for (int s = 0; s < 11; s++) {
        int o4 = tid + s*256;
        int a = o4 >> 7, c4 = o4 & 127, hd = c4 >> 5;
        #pragma unroll
        for (int j = 0; j < AA; j++) {
            float al = alpha1[(a*AA+j)*4 + hd];
            unsigned long long aa = f2pack(al, al);
            ulonglong2 hv = *(const ulonglong2*)&h1_4[j*128 + c4];
            f2fma(o01[s], hv.x, aa);
            f2fma(o23[s], hv.y, aa);
        }
    }
    __syncthreads();
    #pragma unroll
    for (int s = 0; s < 11; s++) {
        int o4 = tid + s*256;
        int c4 = o4 & 127;
        float4 bv = b1_4[c4];
        float vx, vy, vz, vw;
        f2unpack(o01[s], vx, vy);
        f2unpack(o23[s], vz, vw);
        float4 v;
        v.x = fmaxf(vx + bv.x, 0.f);
        v.y = fmaxf(vy + bv.y, 0.f);
        v.z = fmaxf(vz + bv.z, 0.f);
        v.w = fmaxf(vw + bv.w, 0.f);
        h1_4[o4] = v;
    }
    __syncthreads();

    {
        int c = tid & 127, ih = tid >> 7;
        int i0 = ih * 11;
        unsigned long long acc2[11];
        #pragma unroll
        for (int ii = 0; ii < 11; ii++) acc2[ii] = 0ull;
        for (int k4 = 0; k4 < 128; k4++) {
            int k = k4*4;
            float w0 = W2[(k+0)*CC + c];
            float w1 = W2[(k+1)*CC + c];
            float w2 = W2[(k+2)*CC + c];
            float w3 = W2[(k+3)*CC + c];
            unsigned long long w01 = f2pack(w0, w1);
            unsigned long long w23 = f2pack(w2, w3);
            #pragma unroll
            for (int ii = 0; ii < 11; ii++) {
                ulonglong2 xv = *(const ulonglong2*)&h1_4[(i0+ii)*128 + k4];
                f2fma(acc2[ii], xv.x, w01);
                f2fma(acc2[ii], xv.y, w23);
            }
        }
        #pragma unroll
        for (int ii = 0; ii < 11; ii++) h2[(i0+ii)*CC + c] = f2sum(acc2[ii]);
    }
    __syncthreads();

    if (tid < 44) {
        int i = tid % AA; bool dst = (tid >= AA);
        const float4* att4 = (const float4*)(dst ? aD2 : aS2);
        const float4* h2_4 = (const float4*)h2;
        float a0=0.f,a1=0.f,a2=0.f,a3=0.f;
        #pragma unroll 8
        for (int q = 0; q < 32; q++) {
            float4 h = h2_4[i*32 + q];
            float4 w = att4[q];
            a0 += h.x*w.x; a1 += h.y*w.y; a2 += h.z*w.z; a3 += h.w*w.w;
        }
        (dst ? a2d : a2s)[i] = (a0+a1)+(a2+a3);
    }
    __syncthreads();
    if (tid < AA) {
        int i = tid;
        float di = a2d[i];
        float e[AA]; float m = -1e30f;
        #pragma unroll
        for (int j = 0; j < AA; j++) {
            float v = di + a2s[j];
            v = (v > 0.f) ? v : 0.2f*v;
            e[j] = v; m = fmaxf(m, v);
        }
        float ssum = 0.f;
        #pragma unroll
        for (int j = 0; j < AA; j++) { float ex = __expf(e[j]-m); e[j] = ex; ssum += ex; }
        float inv = 1.f/ssum;
        #pragma unroll
        for (int j = 0; j < AA; j++) alpha2[i*AA+j] = e[j]*inv;
    }
    __syncthreads();

    {
        int c = tid & 127, ih = tid >> 7;
        float bc = b2[c];
        float s = 0.f;
        for (int i = ih*11; i < ih*11 + 11; i++) {
            float acc = bc;
            #pragma unroll
            for (int j = 0; j < AA; j++) acc += alpha2[i*AA+j] * h2[j*CC + c];
            s += fmaxf(acc, 0.f);
        }
        psum[ih*128 + c] = s;
    }
    __syncthreads();
    if (tid < CC)
        pooled[(long)n*CC + tid] = (psum[tid] + psum[128 + tid]) * (1.f/22.f);
    __syncthreads();
}

// ---------------- 16-row gathered GEMM (proven inner loop) ----------------
__device__ void gemm16_rows(const float* __restrict__ X, long xbase, long xstride,
                            int K, int kshift,
                            const float* __restrict__ W,
                            const float* __restrict__ bi, const float* __restrict__ bh,
                            float* __restrict__ out, long obase, long ostride,
                            float* xsm, int tid)
{
    __syncthreads();
    const int kmask = K - 1;
    for (int idx = tid; idx < 16*K; idx += 256) {
        int r = idx >> kshift, c = idx & kmask;
        xsm[idx] = X[xbase + (long)r*xstride + c];
    }
    __syncthreads();

    float acc[16][4];
    #pragma unroll
    for (int nn = 0; nn < 16; nn++) { acc[nn][0]=0.f; acc[nn][1]=0.f; acc[nn][2]=0.f; acc[nn][3]=0.f; }

    const int r0 = tid, r1 = tid+256, r2 = tid+512, r3 = tid+768;
    for (int k = 0; k < K; k += 4) {
        float4 w0 = *(const float4*)&W[(long)r0*K + k];
        float4 w1 = *(const float4*)&W[(long)r1*K + k];
        float4 w2 = *(const float4*)&W[(long)r2*K + k];
        float4 w3 = *(const float4*)&W[(long)r3*K + k];
        #pragma unroll
        for (int nn = 0; nn < 16; nn++) {
            float4 xv = *(const float4*)&xsm[(nn << kshift) + k];
            acc[nn][0] += xv.x*w0.x + xv.y*w0.y + xv.z*w0.z + xv.w*w0.w;
            acc[nn][1] += xv.x*w1.x + xv.y*w1.y + xv.z*w1.z + xv.w*w1.w;
            acc[nn][2] += xv.x*w2.x + xv.y*w2.y + xv.z*w2.z + xv.w*w2.w;
            acc[nn][3] += xv.x*w3.x + xv.y*w3.y + xv.z*w3.z + xv.w*w3.w;
        }
    }
    float bs0 = bi[r0]+bh[r0], bs1 = bi[r1]+bh[r1], bs2 = bi[r2]+bh[r2], bs3 = bi[r3]+bh[r3];
    #pragma unroll
    for (int nn = 0; nn < 16; nn++) {
        long base = obase + (long)nn*ostride;
        out[base + r0] = acc[nn][0] + bs0;
        out[base + r1] = acc[nn][1] + bs1;
        out[base + r2] = acc[nn][2] + bs2;
        out[base + r3] = acc[nn][3] + bs3;
    }
    __syncthreads();
}

// publish pattern: stores ... -> fence (all threads) -> sync -> tid0 flag
__device__ __forceinline__ void publish(unsigned* flag, int tid)
{
    __threadfence();
    __syncthreads();
    if (tid == 0) atomicAdd(flag, 1u);
}

// ---------------- LSTM epoch barrier (128 participants, proven) -----------
__device__ __forceinline__ void grid_barrier_epoch(unsigned target)
{
    __threadfence();
    __syncthreads();
    if (threadIdx.x == 0) {
        unsigned prev = atomicAdd(&g_bar_count, 1u);
        if (prev == (unsigned)(LSTM_BLOCKS - 1)) {
            g_bar_count = 0u;
            __threadfence();
            g_bar_epoch = target;
        } else {
            while (g_bar_epoch < target) { }
        }
        __threadfence();
    }
    __syncthreads();
}

// ---------------- megakernel: LSTM + unified producer role -----------------
extern "C" __global__ void __launch_bounds__(256, 2)
mega(const float* __restrict__ feat,
     const float* __restrict__ W1, const float* __restrict__ aS1,
     const float* __restrict__ aD1, const float* __restrict__ b1,
     const float* __restrict__ W2, const float* __restrict__ aS2,
     const float* __restrict__ aD2, const float* __restrict__ b2,
     const float* __restrict__ Wih0, const float* __restrict__ Whh0,
     const float* __restrict__ bih0, const float* __restrict__ bhh0,
     const float* __restrict__ Wih1, const float* __restrict__ Whh1,
     const float* __restrict__ bih1, const float* __restrict__ bhh1,
     const int* __restrict__ slen)
{
    extern __shared__ float sm[];
    __shared__ unsigned s_claim;
    const int bid = blockIdx.x;
    const int tid = threadIdx.x;

    if (bid < LSTM_BLOCKS) {
        // ======== LSTM role: block owns units {2*bid, 2*bid+1}, 2 phases ====
        float* ws  = sm;            // 8 x 260
        float* hs  = sm + 2080;     // 32 x 256
        float* gsm = sm + 10272;    // 32 x 8

        const int b = tid >> 3, r = tid & 7;
        const int myj = (r >> 1)*256 + bid*2 + (r & 1);
        const int u   = bid*2 + (r & 1);
        const int mylen = read_len(slen, b);

        for (int phase = 0; phase < 2; phase++) {
            const float* Whh = phase ? Whh1 : Whh0;
            const float* xg  = phase ? g_xg1 : g_xg0;
            float* hbuf      = phase ? g_h1buf : g_h0buf;
            volatile unsigned* ready = phase ? (volatile unsigned*)g_xg1ready
                                             : (volatile unsigned*)g_xg0ready;
            __syncthreads();
            for (int idx = tid; idx < 8*256; idx += 256) {
                int q = idx >> 8, k = idx & 255;
                int j = (q >> 1)*256 + bid*2 + (q & 1);
                ws[q*260 + k] = Whh[j*256 + k];
            }
            float creg = 0.f;
            __syncthreads();

            for (int t = 0; t < TT; t++) {
                if (tid == 0) { while (ready[t] < 2u) { } }
                __syncthreads();

                const float* hprev = hbuf + (t & 1)*BB*HID;
                for (int idx = tid*4; idx < BB*HID; idx += 1024)
                    *(float4*)&hs[idx] = *(const float4*)&hprev[idx];
                __syncthreads();

                float xn = xg[(long)(b*TT + t)*G4 + myj];
                float a0=0.f,a1=0.f,a2=0.f,a3=0.f;
                #pragma unroll 8
                for (int k = 0; k < HID; k += 4) {
                    float4 h4 = *(const float4*)&hs[b*HID + k];
                    float4 w4 = *(const float4*)&ws[r*260 + k];
                    a0 += h4.x*w4.x; a1 += h4.y*w4.y; a2 += h4.z*w4.z; a3 += h4.w*w4.w;
                }
                gsm[b*8 + r] = (a0+a1)+(a2+a3) + xn;
                __syncthreads();

                if (r < 2) {
                    float gi = sig_fast (gsm[b*8 + 0 + r]);
                    float gf = sig_fast (gsm[b*8 + 2 + r]);
                    float gg = tanh_fast(gsm[b*8 + 4 + r]);
                    float go = sig_fast (gsm[b*8 + 6 + r]);
                    float cn = gf*creg + gi*gg;
                    float hn = go * tanh_fast(cn);
                    if (t >= mylen) { cn = creg; hn = hs[b*HID + u]; }
                    creg = cn;
                    hbuf[((t+1)&1)*BB*HID + b*HID + u] = hn;
                    if (phase == 0) g_h0seq[(long)(b*TT + t)*HID + u] = hn;
                    else if (t == TT-1) g_hlast[b*HID + u] = hn;
                }
                grid_barrier_epoch((unsigned)(phase*TT + t + 1));
                if (phase == 0 && bid == 0 && tid == 0) g_h0done = (unsigned)(t + 1);
            }
        }
    } else {
        // ======== unified producer role: gat + gemm0 queue, then gemm1 ======
        for (;;) {
            if (tid == 0) s_claim = atomicAdd(&g_prodctr, 1u);
            __syncthreads();
            unsigned ib = s_claim;
            __syncthreads();
            if (ib >= (unsigned)QITEMS) break;
            int t = (int)(ib / 34u), j = (int)(ib % 34u);
            if (j < 32) {
                // GAT frame (batch j, time t)
                gat_frame(j*TT + t, sm, tid, feat, W1, aS1, aD1, b1,
                          W2, aS2, aD2, b2, g_pooled);
                publish(&g_gatdone[t], tid);
            } else {
                // gemm0 half (j-32) for time t — wait all 32 frames of t
                if (tid == 0) {
                    volatile unsigned* gd = (volatile unsigned*)g_gatdone;
                    while (gd[t] < 32u) { }
                }
                __syncthreads();
                int h = j - 32;
                long xbase = ((long)(h*16)*TT + t)*CC;
                long obase = ((long)(h*16)*TT + t)*G4;
                gemm16_rows(g_pooled, xbase, (long)TT*CC, CC, 7,
                            Wih0, bih0, bhh0, g_xg0, obase, (long)TT*G4, sm, tid);
                publish(&g_xg0ready[t], tid);
            }
        }
        // gemm1 tasks (gated on LSTM phase-0 progress; monotonic, no cycle)
        for (;;) {
            if (tid == 0) s_claim = atomicAdd(&g_m1ctr, 1u);
            __syncthreads();
            unsigned m = s_claim;
            __syncthreads();
            if (m >= 512u) break;
            int t = (int)(m >> 1), h = (int)(m & 1u);
            if (tid == 0) { while (g_h0done <= (unsigned)t) { } }
            __syncthreads();
            long xbase = ((long)(h*16)*TT + t)*HID;
            long obase = ((long)(h*16)*TT + t)*G4;
            gemm16_rows(g_h0seq, xbase, (long)TT*HID, HID, 8,
                        Wih1, bih1, bhh1, g_xg1, obase, (long)TT*G4, sm, tid);
            publish(&g_xg1ready[t], tid);
        }
    }
}

extern "C" __global__ void zero_init()
{
    int i = blockIdx.x*256 + threadIdx.x;
    if (i < 2*BB*HID) { g_h0buf[i] = 0.f; g_h1buf[i] = 0.f; }
    if (i < TT) { g_gatdone[i] = 0u; g_xg0ready[i] = 0u; g_xg1ready[i] = 0u; }
    if (i == 0) {
        g_bar_count = 0u; g_bar_epoch = 0u;
        g_prodctr = 0u; g_m1ctr = 0u;
        g_h0done = 0u;
    }
}

extern "C" __global__ void final_kernel(const float* __restrict__ w,
                                        const float* __restrict__ bias,
                                        float* __restrict__ out)
{
    const int tid = threadIdx.x;
    const int b = tid >> 3, l = tid & 7;
    float s = 0.f;
    for (int k = l; k < HID; k += 8) s += g_hlast[b*HID + k] * w[k];
    s += __shfl_xor_sync(0xffffffffu, s, 4);
    s += __shfl_xor_sync(0xffffffffu, s, 2);
    s += __shfl_xor_sync(0xffffffffu, s, 1);
    if (l == 0) out[b] = s + bias[0];
}

// ---------------- launch ----------------
extern "C" void kernel_launch(void* const* d_in, const int* in_sizes, int n_in,
                              void* d_out, int out_size)
{
    const float* feat = (const float*)d_in[0];
    const int*   slen = (const int*)d_in[1];
    const float* W1   = (const float*)d_in[2];
    const float* aS1  = (const float*)d_in[3];
    const float* aD1  = (const float*)d_in[4];
    const float* b1   = (const float*)d_in[5];
    const float* W2   = (const float*)d_in[6];
    const float* aS2  = (const float*)d_in[7];
    const float* aD2  = (const float*)d_in[8];
    const float* b2   = (const float*)d_in[9];
    const float* Wih0 = (const float*)d_in[10];
    const float* Whh0 = (const float*)d_in[11];
    const float* bih0 = (const float*)d_in[12];
    const float* bhh0 = (const float*)d_in[13];
    const float* Wih1 = (const float*)d_in[14];
    const float* Whh1 = (const float*)d_in[15];
    const float* bih1 = (const float*)d_in[16];
    const float* bhh1 = (const float*)d_in[17];
    const float* clfw = (const float*)d_in[18];
    const float* clfb = (const float*)d_in[19];
    float* out = (float*)d_out;

    cudaFuncSetAttribute(mega, cudaFuncAttributeMaxDynamicSharedMemorySize, MEGA_SMEM_BYTES);

    // 1) reset all cross-role sync state + h buffers (graph-replay safe)
    zero_init<<<(2*BB*HID + 255)/256, 256>>>();

    // 2) overlapped GAT + input GEMMs + 2-layer LSTM (starvation-proof roles)
    mega<<<GRID_TOTAL, 256, MEGA_SMEM_BYTES>>>(
        feat, W1, aS1, aD1, b1, W2, aS2, aD2, b2,
        Wih0, Whh0, bih0, bhh0, Wih1, Whh1, bih1, bhh1, slen);

    // 3) classifier
    final_kernel<<<1, 256>>>(clfw, clfb, out);
}